// round 5
// baseline (speedup 1.0000x reference)
#include <cuda_runtime.h>
#include <math.h>

// ---------------------------------------------------------------------------
// Problem constants (fixed shapes from reference)
// ---------------------------------------------------------------------------
#define BB   128      // batch
#define SS   336      // src seq len
#define IND  64       // encoder input dim
#define HH   1024     // hidden
#define TT   96       // target len
#define XDIM 1025     // decoder input dim (OUT + H)

// ---------------------------------------------------------------------------
// Scratch (device globals: allocation-free, graph-capture safe)
// ---------------------------------------------------------------------------
__device__ float g_h[2][BB * HH];                    // hidden double buffer
__device__ float g_c[2][BB * HH];                    // cell double buffer
__device__ float g_enc[(size_t)BB * SS * HH];        // encoder outputs [B,S,H] (176 MB)
__device__ float g_qpart[4][BB * HH];                // K-split partials of q = h @ attn_W^T
__device__ float g_x[BB * XDIM];                     // decoder input [prev_y, ctx]

// ---------------------------------------------------------------------------
// init: zero h0, c0, prev_y (and ctx slots; harmless)
// ---------------------------------------------------------------------------
__global__ void init_kernel() {
    int i = blockIdx.x * blockDim.x + threadIdx.x;
    if (i < BB * HH) { g_h[0][i] = 0.f; g_c[0][i] = 0.f; }
    if (i < BB * XDIM) g_x[i] = 0.f;
}

__device__ __forceinline__ float sigf(float v) { return 1.f / (1.f + expf(-v)); }

// ---------------------------------------------------------------------------
// Fused LSTM step.  Grid = 128 CTAs; CTA owns hidden units [8*blk, 8*blk+8)
// across all 4 gates -> computes a [128 x 32] slice of the [128 x 4096] gate
// matrix, then does the cell pointwise locally.
// Tiling: M=128, N=32, K in 32-slices. 256 threads, 4x4 frags/thread.
// ---------------------------------------------------------------------------
__global__ __launch_bounds__(256)
void lstm_step_kernel(const float* __restrict__ x, int x_stride, int KX,
                      const float* __restrict__ Wih,
                      const float* __restrict__ h_in,
                      const float* __restrict__ Whh,
                      const float* __restrict__ b_ih,
                      const float* __restrict__ b_hh,
                      const float* __restrict__ c_in,
                      float* __restrict__ h_out,
                      float* __restrict__ c_out,
                      float* __restrict__ enc_out)   // nullable; pre-offset by t*H
{
    __shared__ float sA[128][33];   // activation tile [batch][k]
    __shared__ float sB[32][33];    // weight tile [col][k]

    const int tid = threadIdx.x;
    const int tm  = tid & 31;       // batch lane
    const int tn  = tid >> 5;       // hidden-unit within CTA (0..7)
    const int j0  = blockIdx.x * 8; // first hidden unit of this CTA

    float acc[4][4];
#pragma unroll
    for (int i = 0; i < 4; ++i)
#pragma unroll
        for (int j = 0; j < 4; ++j) acc[i][j] = 0.f;

    // -------- phase 1: x @ W_ih^T (masked tail for KX=1025) --------
    const int ntx = (KX + 31) >> 5;
    for (int tile = 0; tile < ntx; ++tile) {
        const int k0 = tile << 5;
#pragma unroll
        for (int r = 0; r < 16; ++r) {               // 4096 elems of A
            int idx = tid + r * 256;
            int b = idx >> 5, kk = idx & 31;
            int k = k0 + kk;
            sA[b][kk] = (k < KX) ? x[(size_t)b * x_stride + k] : 0.f;
        }
#pragma unroll
        for (int r = 0; r < 4; ++r) {                // 1024 elems of B
            int idx = tid + r * 256;
            int c = idx >> 5, kk = idx & 31;
            int k = k0 + kk;
            int row = (c >> 3) * HH + j0 + (c & 7);  // gate*H + unit
            sB[c][kk] = (k < KX) ? Wih[(size_t)row * KX + k] : 0.f;
        }
        __syncthreads();
#pragma unroll
        for (int kk = 0; kk < 32; ++kk) {
            float a0 = sA[tm][kk], a1 = sA[tm + 32][kk];
            float a2 = sA[tm + 64][kk], a3 = sA[tm + 96][kk];
            float w0 = sB[tn][kk],      w1 = sB[tn + 8][kk];
            float w2 = sB[tn + 16][kk], w3 = sB[tn + 24][kk];
            acc[0][0] += a0 * w0; acc[0][1] += a0 * w1; acc[0][2] += a0 * w2; acc[0][3] += a0 * w3;
            acc[1][0] += a1 * w0; acc[1][1] += a1 * w1; acc[1][2] += a1 * w2; acc[1][3] += a1 * w3;
            acc[2][0] += a2 * w0; acc[2][1] += a2 * w1; acc[2][2] += a2 * w2; acc[2][3] += a2 * w3;
            acc[3][0] += a3 * w0; acc[3][1] += a3 * w1; acc[3][2] += a3 * w2; acc[3][3] += a3 * w3;
        }
        __syncthreads();
    }

    // -------- phase 2: h @ W_hh^T (K = 1024, unmasked) --------
    for (int tile = 0; tile < 32; ++tile) {
        const int k0 = tile << 5;
#pragma unroll
        for (int r = 0; r < 16; ++r) {
            int idx = tid + r * 256;
            int b = idx >> 5, kk = idx & 31;
            sA[b][kk] = h_in[(size_t)b * HH + k0 + kk];
        }
#pragma unroll
        for (int r = 0; r < 4; ++r) {
            int idx = tid + r * 256;
            int c = idx >> 5, kk = idx & 31;
            int row = (c >> 3) * HH + j0 + (c & 7);
            sB[c][kk] = Whh[(size_t)row * HH + k0 + kk];
        }
        __syncthreads();
#pragma unroll
        for (int kk = 0; kk < 32; ++kk) {
            float a0 = sA[tm][kk], a1 = sA[tm + 32][kk];
            float a2 = sA[tm + 64][kk], a3 = sA[tm + 96][kk];
            float w0 = sB[tn][kk],      w1 = sB[tn + 8][kk];
            float w2 = sB[tn + 16][kk], w3 = sB[tn + 24][kk];
            acc[0][0] += a0 * w0; acc[0][1] += a0 * w1; acc[0][2] += a0 * w2; acc[0][3] += a0 * w3;
            acc[1][0] += a1 * w0; acc[1][1] += a1 * w1; acc[1][2] += a1 * w2; acc[1][3] += a1 * w3;
            acc[2][0] += a2 * w0; acc[2][1] += a2 * w1; acc[2][2] += a2 * w2; acc[2][3] += a2 * w3;
            acc[3][0] += a3 * w0; acc[3][1] += a3 * w1; acc[3][2] += a3 * w2; acc[3][3] += a3 * w3;
        }
        __syncthreads();
    }

    // -------- pointwise LSTM cell (i,f,g,o order) --------
    const int u = j0 + tn;
    const float bi = b_ih[u]          + b_hh[u];
    const float bf = b_ih[HH + u]     + b_hh[HH + u];
    const float bg = b_ih[2 * HH + u] + b_hh[2 * HH + u];
    const float bo = b_ih[3 * HH + u] + b_hh[3 * HH + u];
#pragma unroll
    for (int i = 0; i < 4; ++i) {
        const int b = tm + 32 * i;
        float gi = acc[i][0] + bi;
        float gf = acc[i][1] + bf;
        float gg = acc[i][2] + bg;
        float go = acc[i][3] + bo;
        float co = c_in[(size_t)b * HH + u];
        float cn = sigf(gf) * co + sigf(gi) * tanhf(gg);
        float hn = sigf(go) * tanhf(cn);
        h_out[(size_t)b * HH + u] = hn;
        c_out[(size_t)b * HH + u] = cn;
        if (enc_out) enc_out[(size_t)b * SS * HH + u] = hn;
    }
}

// ---------------------------------------------------------------------------
// D1: q = h @ attn_W^T, K-split x4 into g_qpart.  Grid = 128 CTAs:
//   blockIdx>>5 = K slice (256 wide), blockIdx&31 = 32-col N chunk.
// ---------------------------------------------------------------------------
__global__ __launch_bounds__(256)
void qgemm_kernel(const float* __restrict__ h,
                  const float* __restrict__ attnW,
                  float* __restrict__ qpart)
{
    __shared__ float sA[128][33];
    __shared__ float sB[32][33];
    const int tid = threadIdx.x;
    const int tm  = tid & 31;
    const int tn  = tid >> 5;
    const int ks  = blockIdx.x >> 5;
    const int n0  = (blockIdx.x & 31) << 5;

    float acc[4][4];
#pragma unroll
    for (int i = 0; i < 4; ++i)
#pragma unroll
        for (int j = 0; j < 4; ++j) acc[i][j] = 0.f;

    for (int tile = 0; tile < 8; ++tile) {
        const int k0 = ks * 256 + tile * 32;
#pragma unroll
        for (int r = 0; r < 16; ++r) {
            int idx = tid + r * 256;
            int b = idx >> 5, kk = idx & 31;
            sA[b][kk] = h[(size_t)b * HH + k0 + kk];
        }
#pragma unroll
        for (int r = 0; r < 4; ++r) {
            int idx = tid + r * 256;
            int c = idx >> 5, kk = idx & 31;
            sB[c][kk] = attnW[(size_t)(n0 + c) * HH + k0 + kk];
        }
        __syncthreads();
#pragma unroll
        for (int kk = 0; kk < 32; ++kk) {
            float a0 = sA[tm][kk], a1 = sA[tm + 32][kk];
            float a2 = sA[tm + 64][kk], a3 = sA[tm + 96][kk];
            float w0 = sB[tn][kk],      w1 = sB[tn + 8][kk];
            float w2 = sB[tn + 16][kk], w3 = sB[tn + 24][kk];
            acc[0][0] += a0 * w0; acc[0][1] += a0 * w1; acc[0][2] += a0 * w2; acc[0][3] += a0 * w3;
            acc[1][0] += a1 * w0; acc[1][1] += a1 * w1; acc[1][2] += a1 * w2; acc[1][3] += a1 * w3;
            acc[2][0] += a2 * w0; acc[2][1] += a2 * w1; acc[2][2] += a2 * w2; acc[2][3] += a2 * w3;
            acc[3][0] += a3 * w0; acc[3][1] += a3 * w1; acc[3][2] += a3 * w2; acc[3][3] += a3 * w3;
        }
        __syncthreads();
    }

    float* qo = qpart + (size_t)ks * BB * HH;
#pragma unroll
    for (int i = 0; i < 4; ++i)
#pragma unroll
        for (int j = 0; j < 4; ++j)
            qo[(size_t)(tm + 32 * i) * HH + n0 + tn + 8 * j] = acc[i][j];
}

// ---------------------------------------------------------------------------
// D2: Luong attention, flash-style single pass over S.
// Grid = 128 (one CTA per batch), 256 threads = 8 warps; warp w owns
// s = w + 8*it.  Per-warp online softmax + ctx accumulator, merged at end.
// Writes ctx into g_x[b][1..1024].  Also sums the 4 q partials.
// ---------------------------------------------------------------------------
__global__ __launch_bounds__(256)
void attn_kernel(const float* __restrict__ qpart,
                 const float* __restrict__ enc,
                 float* __restrict__ xbuf)
{
    const int b    = blockIdx.x;
    const int tid  = threadIdx.x;
    const int w    = tid >> 5;
    const int lane = tid & 31;

    __shared__ float sm_ctx[8][1024];
    __shared__ float sm_m[8], sm_d[8];

    // q[b] (full 1024 per warp), summing the 4 K-split partials
    float4 q4[8], ctx4[8];
    const float4* p0 = (const float4*)(qpart + 0 * (size_t)BB * HH + (size_t)b * HH);
    const float4* p1 = (const float4*)(qpart + 1 * (size_t)BB * HH + (size_t)b * HH);
    const float4* p2 = (const float4*)(qpart + 2 * (size_t)BB * HH + (size_t)b * HH);
    const float4* p3 = (const float4*)(qpart + 3 * (size_t)BB * HH + (size_t)b * HH);
#pragma unroll
    for (int i = 0; i < 8; ++i) {
        int idx = lane + 32 * i;
        float4 a = p0[idx], c = p1[idx], d = p2[idx], e = p3[idx];
        q4[i].x = a.x + c.x + d.x + e.x;
        q4[i].y = a.y + c.y + d.y + e.y;
        q4[i].z = a.z + c.z + d.z + e.z;
        q4[i].w = a.w + c.w + d.w + e.w;
        ctx4[i] = make_float4(0.f, 0.f, 0.f, 0.f);
    }

    float m = -1e30f, d = 0.f;
    const float4* erow = (const float4*)(enc + (size_t)b * SS * HH);

    for (int it = 0; it < SS / 8; ++it) {
        const int s = w + 8 * it;
        const float4* er = erow + (size_t)s * (HH / 4);
        float4 e4[8];
#pragma unroll
        for (int i = 0; i < 8; ++i) e4[i] = er[lane + 32 * i];

        float p = 0.f;
#pragma unroll
        for (int i = 0; i < 8; ++i)
            p += q4[i].x * e4[i].x + q4[i].y * e4[i].y +
                 q4[i].z * e4[i].z + q4[i].w * e4[i].w;
#pragma unroll
        for (int off = 16; off >= 1; off >>= 1)
            p += __shfl_xor_sync(0xffffffffu, p, off);

        float mn = fmaxf(m, p);
        float sc = expf(m - mn);
        float wv = expf(p - mn);
        d = d * sc + wv;
#pragma unroll
        for (int i = 0; i < 8; ++i) {
            ctx4[i].x = ctx4[i].x * sc + wv * e4[i].x;
            ctx4[i].y = ctx4[i].y * sc + wv * e4[i].y;
            ctx4[i].z = ctx4[i].z * sc + wv * e4[i].z;
            ctx4[i].w = ctx4[i].w * sc + wv * e4[i].w;
        }
        m = mn;
    }

    // merge the 8 per-warp streams
#pragma unroll
    for (int i = 0; i < 8; ++i)
        ((float4*)sm_ctx[w])[lane + 32 * i] = ctx4[i];
    if (lane == 0) { sm_m[w] = m; sm_d[w] = d; }
    __syncthreads();

    float mstar = sm_m[0];
#pragma unroll
    for (int ww = 1; ww < 8; ++ww) mstar = fmaxf(mstar, sm_m[ww]);
    float ew[8], dtot = 0.f;
#pragma unroll
    for (int ww = 0; ww < 8; ++ww) { ew[ww] = expf(sm_m[ww] - mstar); dtot += sm_d[ww] * ew[ww]; }
    const float inv = 1.f / dtot;

    float4 cx = make_float4(0.f, 0.f, 0.f, 0.f);
#pragma unroll
    for (int ww = 0; ww < 8; ++ww) {
        float4 v = ((float4*)sm_ctx[ww])[tid];
        cx.x += v.x * ew[ww]; cx.y += v.y * ew[ww];
        cx.z += v.z * ew[ww]; cx.w += v.w * ew[ww];
    }
    float* xo = xbuf + (size_t)b * XDIM + 1 + 4 * tid;
    xo[0] = cx.x * inv; xo[1] = cx.y * inv; xo[2] = cx.z * inv; xo[3] = cx.w * inv;
}

// ---------------------------------------------------------------------------
// D4: pred = h @ fc_W^T + fc_b (OUT=1); writes out[b, t] and prev_y slot.
// Grid = 128 (batch), block = 32 (one warp).
// ---------------------------------------------------------------------------
__global__ void fc_kernel(const float* __restrict__ h,
                          const float* __restrict__ fcW,
                          const float* __restrict__ fcb,
                          float* __restrict__ out,
                          float* __restrict__ xbuf, int t)
{
    const int b = blockIdx.x;
    const int lane = threadIdx.x;
    float s = 0.f;
#pragma unroll
    for (int i = 0; i < 32; ++i) {
        int k = lane + 32 * i;
        s += h[(size_t)b * HH + k] * fcW[k];
    }
#pragma unroll
    for (int off = 16; off >= 1; off >>= 1)
        s += __shfl_xor_sync(0xffffffffu, s, off);
    if (lane == 0) {
        float p = s + fcb[0];
        out[(size_t)b * TT + t] = p;
        xbuf[(size_t)b * XDIM] = p;
    }
}

// ---------------------------------------------------------------------------
// kernel_launch: graph-capturable sequence of launches (default stream).
// ---------------------------------------------------------------------------
extern "C" void kernel_launch(void* const* d_in, const int* in_sizes, int n_in,
                              void* d_out, int out_size)
{
    const float* src   = (const float*)d_in[0];
    const float* eWih  = (const float*)d_in[1];
    const float* eWhh  = (const float*)d_in[2];
    const float* ebih  = (const float*)d_in[3];
    const float* ebhh  = (const float*)d_in[4];
    const float* dWih  = (const float*)d_in[5];
    const float* dWhh  = (const float*)d_in[6];
    const float* dbih  = (const float*)d_in[7];
    const float* dbhh  = (const float*)d_in[8];
    const float* attnW = (const float*)d_in[9];
    const float* fcW   = (const float*)d_in[10];
    const float* fcb   = (const float*)d_in[11];
    float* out = (float*)d_out;

    float *hb, *cb, *encb, *qp, *xb;
    cudaGetSymbolAddress((void**)&hb,   g_h);
    cudaGetSymbolAddress((void**)&cb,   g_c);
    cudaGetSymbolAddress((void**)&encb, g_enc);
    cudaGetSymbolAddress((void**)&qp,   g_qpart);
    cudaGetSymbolAddress((void**)&xb,   g_x);

    float* hbuf[2] = { hb, hb + BB * HH };
    float* cbuf[2] = { cb, cb + BB * HH };

    init_kernel<<<(BB * XDIM + 255) / 256, 256>>>();

    // ---- encoder: 336 steps ----
    for (int t = 0; t < SS; ++t) {
        int p = t & 1;
        lstm_step_kernel<<<HH / 8, 256>>>(
            src + (size_t)t * IND, SS * IND, IND, eWih,
            hbuf[p], eWhh, ebih, ebhh, cbuf[p],
            hbuf[1 - p], cbuf[1 - p],
            encb + (size_t)t * HH);
    }

    // after 336 steps, state lives in buffer 0
    // ---- decoder: 96 steps ----
    for (int t = 0; t < TT; ++t) {
        int p = t & 1;
        qgemm_kernel<<<128, 256>>>(hbuf[p], attnW, qp);
        attn_kernel<<<BB, 256>>>(qp, encb, xb);
        lstm_step_kernel<<<HH / 8, 256>>>(
            xb, XDIM, XDIM, dWih,
            hbuf[p], dWhh, dbih, dbhh, cbuf[p],
            hbuf[1 - p], cbuf[1 - p],
            (float*)nullptr);
        fc_kernel<<<BB, 32>>>(hbuf[1 - p], fcW, fcb, out, xb, t);
    }
}

// round 6
// speedup vs baseline: 1.2214x; 1.2214x over previous
#include <cuda_runtime.h>
#include <math.h>

// ---------------------------------------------------------------------------
// Problem constants
// ---------------------------------------------------------------------------
#define BB   128      // batch
#define SS   336      // src seq len
#define IND  64       // encoder input dim
#define HH   1024     // hidden
#define TT   96       // target len
#define XDIM 1025     // decoder input dim (OUT + H)

typedef unsigned long long ull;

// ---------------------------------------------------------------------------
// Scratch (device globals: allocation-free, graph-capture safe)
// ---------------------------------------------------------------------------
__device__ float g_h[2][BB * HH];
__device__ float g_c[2][BB * HH];
__device__ float g_enc[(size_t)BB * SS * HH];     // encoder outputs [B,S,H]
__device__ float g_qpart[4][BB * HH];             // K-split partials of q
__device__ float g_x[BB * XDIM];                  // decoder input [prev_y, ctx]

__global__ void init_kernel() {
    int i = blockIdx.x * blockDim.x + threadIdx.x;
    if (i < BB * HH) { g_h[0][i] = 0.f; g_c[0][i] = 0.f; }
    if (i < BB * XDIM) g_x[i] = 0.f;
}

__device__ __forceinline__ float sigf(float v) { return 1.f / (1.f + expf(-v)); }

// ---- packed fp32x2 helpers (Blackwell FFMA2 path; ptxas won't emit these) ----
__device__ __forceinline__ ull pk2(float x, float y) {
    ull r; asm("mov.b64 %0, {%1,%2};" : "=l"(r) : "f"(x), "f"(y)); return r;
}
__device__ __forceinline__ void fma2(ull& d, ull a, ull b) {
    asm("fma.rn.f32x2 %0, %1, %2, %0;" : "+l"(d) : "l"(a), "l"(b));
}
__device__ __forceinline__ void unpk2(ull v, float& lo, float& hi) {
    asm("mov.b64 {%0,%1}, %2;" : "=f"(lo), "=f"(hi) : "l"(v));
}

// ---------------------------------------------------------------------------
// Register-staged tile loader for the LSTM GEMM.
// A tile: 128 b x 32 k -> ra[16]  (thread: b in {tmA+32*ib}, k = k0+4*kg+j)
// B tile: 32 col x 32 k -> rb[4]  (thread: col = colB, k = k0+kbB+j)
// ---------------------------------------------------------------------------
__device__ __forceinline__ void load_tile(
    int t, int ntx,
    const float* __restrict__ x, int x_stride, int KX, int xvec,
    const float* __restrict__ Wih,
    const float* __restrict__ h_in,
    const float* __restrict__ Whh,
    int tmA, int kg, int rowB, int kbB,
    float ra[16], float rb[4])
{
    if (t < ntx) {
        const int k0 = t * 32;
        if (xvec) {
#pragma unroll
            for (int ib = 0; ib < 4; ++ib) {
                float4 v = *(const float4*)(x + (size_t)(tmA + 32 * ib) * x_stride + k0 + 4 * kg);
                ra[ib*4+0] = v.x; ra[ib*4+1] = v.y; ra[ib*4+2] = v.z; ra[ib*4+3] = v.w;
            }
            float4 wv = *(const float4*)(Wih + (size_t)rowB * KX + k0 + kbB);
            rb[0] = wv.x; rb[1] = wv.y; rb[2] = wv.z; rb[3] = wv.w;
        } else {
#pragma unroll
            for (int ib = 0; ib < 4; ++ib)
#pragma unroll
                for (int j = 0; j < 4; ++j) {
                    int k = k0 + 4 * kg + j;
                    ra[ib*4+j] = (k < KX) ? x[(size_t)(tmA + 32 * ib) * x_stride + k] : 0.f;
                }
#pragma unroll
            for (int j = 0; j < 4; ++j) {
                int k = k0 + kbB + j;
                rb[j] = (k < KX) ? Wih[(size_t)rowB * KX + k] : 0.f;
            }
        }
    } else {
        const int k0 = (t - ntx) * 32;
#pragma unroll
        for (int ib = 0; ib < 4; ++ib) {
            float4 v = *(const float4*)(h_in + (size_t)(tmA + 32 * ib) * HH + k0 + 4 * kg);
            ra[ib*4+0] = v.x; ra[ib*4+1] = v.y; ra[ib*4+2] = v.z; ra[ib*4+3] = v.w;
        }
        float4 wv = *(const float4*)(Whh + (size_t)rowB * HH + k0 + kbB);
        rb[0] = wv.x; rb[1] = wv.y; rb[2] = wv.z; rb[3] = wv.w;
    }
}

// ---------------------------------------------------------------------------
// Fused LSTM step, FFMA2 edition.
// Grid = 128 CTAs; CTA owns hidden units [8*blk, 8*blk+8) across all 4 gates
// -> [128 x 32] slice of the [128 x 4096] gate matrix + local pointwise cell.
// 256 threads; thread = 2 rows x 8 cols = 8 packed FFMA2 accumulators.
// smem: sAt transposed [kk][b] (conflict-free), sBt transposed [kk][col]
// (LDS.64 broadcast pairs). Register-staged double buffering via LDG prefetch.
// ---------------------------------------------------------------------------
__global__ __launch_bounds__(256)
void lstm_step_kernel(const float* __restrict__ x, int x_stride, int KX, int xvec,
                      const float* __restrict__ Wih,
                      const float* __restrict__ h_in,
                      const float* __restrict__ Whh,
                      const float* __restrict__ b_ih,
                      const float* __restrict__ b_hh,
                      const float* __restrict__ c_in,
                      float* __restrict__ h_out,
                      float* __restrict__ c_out,
                      float* __restrict__ enc_out)   // nullable; pre-offset by t*H
{
    __shared__ __align__(16) float sPool[128 * 33]; // GEMM: sAt[kk][b]; epilogue: sG[b][33]
    __shared__ __align__(16) float sBt[32 * 34];    // [kk][col], pad 34

    const int tid = threadIdx.x;
    const int j0  = blockIdx.x * 8;

    // load maps
    const int tmA  = tid & 31, kg = tid >> 5;          // A: b-lane, k-group
    const int colB = tid >> 3, kbB = (tid & 7) * 4;    // B: col, k-offset
    const int rowB = (colB >> 3) * HH + j0 + (colB & 7);
    // compute map
    const int rr = tid & 63;          // rows {rr, rr+64}
    const int cb = (tid >> 6) * 8;    // cols {cb .. cb+7}  (gate = tid>>6)

    const int ntx = (KX + 31) >> 5;
    const int nt  = ntx + 32;

    float ra[16], rb[4];
    ull acc[2][4];
#pragma unroll
    for (int i = 0; i < 2; ++i)
#pragma unroll
        for (int u = 0; u < 4; ++u) acc[i][u] = 0ull;

    load_tile(0, ntx, x, x_stride, KX, xvec, Wih, h_in, Whh, tmA, kg, rowB, kbB, ra, rb);

    for (int t = 0; t < nt; ++t) {
        __syncthreads();               // previous tile's compute done
        // stage regs -> smem (A transposed, conflict-free STS; B transposed)
#pragma unroll
        for (int ib = 0; ib < 4; ++ib)
#pragma unroll
            for (int j = 0; j < 4; ++j)
                sPool[(4 * kg + j) * 128 + tmA + 32 * ib] = ra[ib * 4 + j];
#pragma unroll
        for (int j = 0; j < 4; ++j)
            sBt[(kbB + j) * 34 + colB] = rb[j];
        __syncthreads();

        if (t + 1 < nt)                // prefetch next tile; latency overlaps compute
            load_tile(t + 1, ntx, x, x_stride, KX, xvec, Wih, h_in, Whh,
                      tmA, kg, rowB, kbB, ra, rb);

#pragma unroll 8
        for (int kk = 0; kk < 32; ++kk) {
            float a0 = sPool[kk * 128 + rr];
            float a1 = sPool[kk * 128 + rr + 64];
            ull A0 = pk2(a0, a0);
            ull A1 = pk2(a1, a1);
#pragma unroll
            for (int u = 0; u < 4; ++u) {
                ull Wv = *(const ull*)(sBt + kk * 34 + cb + 2 * u);  // broadcast pair
                fma2(acc[0][u], A0, Wv);
                fma2(acc[1][u], A1, Wv);
            }
        }
    }

    // -------- stage gate values to smem (sG[b][33]) --------
    __syncthreads();
#pragma unroll
    for (int i = 0; i < 2; ++i) {
        const int row = rr + 64 * i;
#pragma unroll
        for (int u = 0; u < 4; ++u) {
            float lo, hi; unpk2(acc[i][u], lo, hi);
            sPool[row * 33 + cb + 2 * u]     = lo;
            sPool[row * 33 + cb + 2 * u + 1] = hi;
        }
    }
    __syncthreads();

    // -------- pointwise LSTM cell (i,f,g,o order) --------
    const int tm = tid & 31, tn = tid >> 5;
    const int u  = j0 + tn;
    const float bi = b_ih[u]          + b_hh[u];
    const float bf = b_ih[HH + u]     + b_hh[HH + u];
    const float bg = b_ih[2 * HH + u] + b_hh[2 * HH + u];
    const float bo = b_ih[3 * HH + u] + b_hh[3 * HH + u];
#pragma unroll
    for (int i = 0; i < 4; ++i) {
        const int b = tm + 32 * i;
        float gi = sPool[b * 33 + tn]      + bi;   // gate 0 (cols 0..7)
        float gf = sPool[b * 33 + 8 + tn]  + bf;   // gate 1
        float gg = sPool[b * 33 + 16 + tn] + bg;   // gate 2
        float go = sPool[b * 33 + 24 + tn] + bo;   // gate 3
        float co = c_in[(size_t)b * HH + u];
        float cn = sigf(gf) * co + sigf(gi) * tanhf(gg);
        float hn = sigf(go) * tanhf(cn);
        h_out[(size_t)b * HH + u] = hn;
        c_out[(size_t)b * HH + u] = cn;
        if (enc_out) enc_out[(size_t)b * SS * HH + u] = hn;
    }
}

// ---------------------------------------------------------------------------
// D1: q = h @ attn_W^T, K-split x4 into g_qpart (unchanged; small).
// ---------------------------------------------------------------------------
__global__ __launch_bounds__(256)
void qgemm_kernel(const float* __restrict__ h,
                  const float* __restrict__ attnW,
                  float* __restrict__ qpart)
{
    __shared__ float sA[128][33];
    __shared__ float sB[32][33];
    const int tid = threadIdx.x;
    const int tm  = tid & 31;
    const int tn  = tid >> 5;
    const int ks  = blockIdx.x >> 5;
    const int n0  = (blockIdx.x & 31) << 5;

    float acc[4][4];
#pragma unroll
    for (int i = 0; i < 4; ++i)
#pragma unroll
        for (int j = 0; j < 4; ++j) acc[i][j] = 0.f;

    for (int tile = 0; tile < 8; ++tile) {
        const int k0 = ks * 256 + tile * 32;
#pragma unroll
        for (int r = 0; r < 16; ++r) {
            int idx = tid + r * 256;
            int b = idx >> 5, kk = idx & 31;
            sA[b][kk] = h[(size_t)b * HH + k0 + kk];
        }
#pragma unroll
        for (int r = 0; r < 4; ++r) {
            int idx = tid + r * 256;
            int c = idx >> 5, kk = idx & 31;
            sB[c][kk] = attnW[(size_t)(n0 + c) * HH + k0 + kk];
        }
        __syncthreads();
#pragma unroll
        for (int kk = 0; kk < 32; ++kk) {
            float a0 = sA[tm][kk], a1 = sA[tm + 32][kk];
            float a2 = sA[tm + 64][kk], a3 = sA[tm + 96][kk];
            float w0 = sB[tn][kk],      w1 = sB[tn + 8][kk];
            float w2 = sB[tn + 16][kk], w3 = sB[tn + 24][kk];
            acc[0][0] += a0 * w0; acc[0][1] += a0 * w1; acc[0][2] += a0 * w2; acc[0][3] += a0 * w3;
            acc[1][0] += a1 * w0; acc[1][1] += a1 * w1; acc[1][2] += a1 * w2; acc[1][3] += a1 * w3;
            acc[2][0] += a2 * w0; acc[2][1] += a2 * w1; acc[2][2] += a2 * w2; acc[2][3] += a2 * w3;
            acc[3][0] += a3 * w0; acc[3][1] += a3 * w1; acc[3][2] += a3 * w2; acc[3][3] += a3 * w3;
        }
        __syncthreads();
    }

    float* qo = qpart + (size_t)ks * BB * HH;
#pragma unroll
    for (int i = 0; i < 4; ++i)
#pragma unroll
        for (int j = 0; j < 4; ++j)
            qo[(size_t)(tm + 32 * i) * HH + n0 + tn + 8 * j] = acc[i][j];
}

// ---------------------------------------------------------------------------
// D2: Luong attention, flash-style, 512 threads (16 warps -> 2x memory
// parallelism per SM).  Warp w owns s = w + 16*it (336 = 16*21).
// Two-round stream merge (16 -> 8 -> final) keeps smem at 32KB.
// ---------------------------------------------------------------------------
__global__ __launch_bounds__(512)
void attn_kernel(const float* __restrict__ qpart,
                 const float* __restrict__ enc,
                 float* __restrict__ xbuf)
{
    const int b    = blockIdx.x;
    const int tid  = threadIdx.x;
    const int w    = tid >> 5;
    const int lane = tid & 31;

    __shared__ __align__(16) float sm_ctx[8][1024];
    __shared__ float sm_m[16], sm_d[16];

    // q[b]: sum the 4 K-split partials (every warp keeps full q in regs)
    float4 q4[8], ctx4[8];
    const float4* p0 = (const float4*)(qpart + 0 * (size_t)BB * HH + (size_t)b * HH);
    const float4* p1 = (const float4*)(qpart + 1 * (size_t)BB * HH + (size_t)b * HH);
    const float4* p2 = (const float4*)(qpart + 2 * (size_t)BB * HH + (size_t)b * HH);
    const float4* p3 = (const float4*)(qpart + 3 * (size_t)BB * HH + (size_t)b * HH);
#pragma unroll
    for (int i = 0; i < 8; ++i) {
        int idx = lane + 32 * i;
        float4 a = p0[idx], c = p1[idx], d = p2[idx], e = p3[idx];
        q4[i].x = a.x + c.x + d.x + e.x;
        q4[i].y = a.y + c.y + d.y + e.y;
        q4[i].z = a.z + c.z + d.z + e.z;
        q4[i].w = a.w + c.w + d.w + e.w;
        ctx4[i] = make_float4(0.f, 0.f, 0.f, 0.f);
    }

    float m = -1e30f, d = 0.f;
    const float4* erow = (const float4*)(enc + (size_t)b * SS * HH);

    for (int it = 0; it < SS / 16; ++it) {
        const int s = w + 16 * it;
        const float4* er = erow + (size_t)s * (HH / 4);
        float4 e4[8];
#pragma unroll
        for (int i = 0; i < 8; ++i) e4[i] = er[lane + 32 * i];

        float p = 0.f;
#pragma unroll
        for (int i = 0; i < 8; ++i)
            p += q4[i].x * e4[i].x + q4[i].y * e4[i].y +
                 q4[i].z * e4[i].z + q4[i].w * e4[i].w;
#pragma unroll
        for (int off = 16; off >= 1; off >>= 1)
            p += __shfl_xor_sync(0xffffffffu, p, off);

        float mn = fmaxf(m, p);
        float sc = expf(m - mn);
        float wv = expf(p - mn);
        d = d * sc + wv;
#pragma unroll
        for (int i = 0; i < 8; ++i) {
            ctx4[i].x = ctx4[i].x * sc + wv * e4[i].x;
            ctx4[i].y = ctx4[i].y * sc + wv * e4[i].y;
            ctx4[i].z = ctx4[i].z * sc + wv * e4[i].z;
            ctx4[i].w = ctx4[i].w * sc + wv * e4[i].w;
        }
        m = mn;
    }

    // ---- merge round 1: fold warps 8..15 into 0..7 ----
    if (w >= 8) {
#pragma unroll
        for (int i = 0; i < 8; ++i)
            ((float4*)sm_ctx[w - 8])[lane + 32 * i] = ctx4[i];
    }
    if (lane == 0) { sm_m[w] = m; sm_d[w] = d; }
    __syncthreads();
    if (w < 8) {
        float m2 = sm_m[w + 8], d2 = sm_d[w + 8];
        float mn = fmaxf(m, m2);
        float s1 = expf(m - mn), s2 = expf(m2 - mn);
        d = d * s1 + d2 * s2;
#pragma unroll
        for (int i = 0; i < 8; ++i) {
            float4 v = ((float4*)sm_ctx[w])[lane + 32 * i];
            ctx4[i].x = ctx4[i].x * s1 + v.x * s2;
            ctx4[i].y = ctx4[i].y * s1 + v.y * s2;
            ctx4[i].z = ctx4[i].z * s1 + v.z * s2;
            ctx4[i].w = ctx4[i].w * s1 + v.w * s2;
        }
        m = mn;
#pragma unroll
        for (int i = 0; i < 8; ++i)
            ((float4*)sm_ctx[w])[lane + 32 * i] = ctx4[i];
        if (lane == 0) { sm_m[w] = m; sm_d[w] = d; }
    }
    __syncthreads();

    // ---- final merge over 8 streams; 512 threads x 2 dims ----
    float mstar = sm_m[0];
#pragma unroll
    for (int ww = 1; ww < 8; ++ww) mstar = fmaxf(mstar, sm_m[ww]);
    float ew[8], dtot = 0.f;
#pragma unroll
    for (int ww = 0; ww < 8; ++ww) { ew[ww] = expf(sm_m[ww] - mstar); dtot += sm_d[ww] * ew[ww]; }
    const float inv = 1.f / dtot;

    float cx0 = 0.f, cx1 = 0.f;
#pragma unroll
    for (int ww = 0; ww < 8; ++ww) {
        float2 v = ((float2*)sm_ctx[ww])[tid];
        cx0 += v.x * ew[ww]; cx1 += v.y * ew[ww];
    }
    float* xo = xbuf + (size_t)b * XDIM + 1 + 2 * tid;
    xo[0] = cx0 * inv; xo[1] = cx1 * inv;
}

// ---------------------------------------------------------------------------
// D4: pred = h @ fc_W^T + fc_b (OUT=1); writes out[b,t] and prev_y slot.
// ---------------------------------------------------------------------------
__global__ void fc_kernel(const float* __restrict__ h,
                          const float* __restrict__ fcW,
                          const float* __restrict__ fcb,
                          float* __restrict__ out,
                          float* __restrict__ xbuf, int t)
{
    const int b = blockIdx.x;
    const int lane = threadIdx.x;
    float s = 0.f;
#pragma unroll
    for (int i = 0; i < 32; ++i) {
        int k = lane + 32 * i;
        s += h[(size_t)b * HH + k] * fcW[k];
    }
#pragma unroll
    for (int off = 16; off >= 1; off >>= 1)
        s += __shfl_xor_sync(0xffffffffu, s, off);
    if (lane == 0) {
        float p = s + fcb[0];
        out[(size_t)b * TT + t] = p;
        xbuf[(size_t)b * XDIM] = p;
    }
}

// ---------------------------------------------------------------------------
// kernel_launch: graph-capturable sequence (default stream).
// ---------------------------------------------------------------------------
extern "C" void kernel_launch(void* const* d_in, const int* in_sizes, int n_in,
                              void* d_out, int out_size)
{
    const float* src   = (const float*)d_in[0];
    const float* eWih  = (const float*)d_in[1];
    const float* eWhh  = (const float*)d_in[2];
    const float* ebih  = (const float*)d_in[3];
    const float* ebhh  = (const float*)d_in[4];
    const float* dWih  = (const float*)d_in[5];
    const float* dWhh  = (const float*)d_in[6];
    const float* dbih  = (const float*)d_in[7];
    const float* dbhh  = (const float*)d_in[8];
    const float* attnW = (const float*)d_in[9];
    const float* fcW   = (const float*)d_in[10];
    const float* fcb   = (const float*)d_in[11];
    float* out = (float*)d_out;

    float *hb, *cb, *encb, *qp, *xb;
    cudaGetSymbolAddress((void**)&hb,   g_h);
    cudaGetSymbolAddress((void**)&cb,   g_c);
    cudaGetSymbolAddress((void**)&encb, g_enc);
    cudaGetSymbolAddress((void**)&qp,   g_qpart);
    cudaGetSymbolAddress((void**)&xb,   g_x);

    float* hbuf[2] = { hb, hb + BB * HH };
    float* cbuf[2] = { cb, cb + BB * HH };

    init_kernel<<<(BB * XDIM + 255) / 256, 256>>>();

    // ---- encoder: 336 steps (x rows 16B-aligned -> vectored loads) ----
    for (int t = 0; t < SS; ++t) {
        int p = t & 1;
        lstm_step_kernel<<<HH / 8, 256>>>(
            src + (size_t)t * IND, SS * IND, IND, /*xvec=*/1, eWih,
            hbuf[p], eWhh, ebih, ebhh, cbuf[p],
            hbuf[1 - p], cbuf[1 - p],
            encb + (size_t)t * HH);
    }

    // ---- decoder: 96 steps (XDIM=1025 -> scalar masked loads for phase 1) ----
    for (int t = 0; t < TT; ++t) {
        int p = t & 1;
        qgemm_kernel<<<128, 256>>>(hbuf[p], attnW, qp);
        attn_kernel<<<BB, 512>>>(qp, encb, xb);
        lstm_step_kernel<<<HH / 8, 256>>>(
            xb, XDIM, XDIM, /*xvec=*/0, dWih,
            hbuf[p], dWhh, dbih, dbhh, cbuf[p],
            hbuf[1 - p], cbuf[1 - p],
            (float*)nullptr);
        fc_kernel<<<BB, 32>>>(hbuf[1 - p], fcW, fcb, out, xb, t);
    }
}